// round 5
// baseline (speedup 1.0000x reference)
#include <cuda_runtime.h>
#include <stdint.h>

#define NB   8
#define NC   64      // CIN == COUT == 64
#define NVP  10242
#define NVT  40962
#define NFC  81920

// scratch (device globals — no allocation allowed)
__device__ float d_xin[(size_t)NB * NVT * NC];     // [b][v][c], padded region = 1.0
__device__ float d_gf [(size_t)NB * NFC * 128];    // [b][f][ew c0..63 | ns c0..63]
__device__ float d_cs [256 * 64];                  // [p][o], p = permuted (k,c) row

// ---------------------------------------------------------------------------
// K0: transpose x [B][C][NVP] -> d_xin [B][v][c], pad v>=NVP with 1.0
// ---------------------------------------------------------------------------
__global__ void k_transpose(const float* __restrict__ x) {
    __shared__ float tile[32][33];
    int b  = blockIdx.z;
    int v0 = blockIdx.x * 32;
    int c0 = blockIdx.y * 32;
    int tx = threadIdx.x, ty = threadIdx.y;   // 32 x 8
    #pragma unroll
    for (int i = 0; i < 4; i++) {
        int c = c0 + ty + i * 8;
        int v = v0 + tx;
        float val = 1.0f;
        if (v < NVP) val = x[((size_t)b * NC + c) * NVP + v];
        tile[ty + i * 8][tx] = val;
    }
    __syncthreads();
    #pragma unroll
    for (int i = 0; i < 4; i++) {
        int v = v0 + ty + i * 8;
        int c = c0 + tx;
        if (v < NVT)
            d_xin[((size_t)b * NVT + v) * NC + c] = tile[tx][ty + i * 8];
    }
}

// ---------------------------------------------------------------------------
// Kc: reorder coeffs [o][c][k] -> d_cs[p][o]
// physical row p = k*64 + j*16 + c4  where channel c = 4*c4 + j
// ---------------------------------------------------------------------------
__global__ void k_coeffs(const float* __restrict__ coeffs) {
    int idx = blockIdx.x * 256 + threadIdx.x;   // 0..16383
    int p = idx >> 6, o = idx & 63;
    int k  = p >> 6;
    int pr = p & 63;
    int j  = pr >> 4;
    int c4 = pr & 15;
    int c  = 4 * c4 + j;
    d_cs[idx] = coeffs[(o * 64 + c) * 4 + k];
}

// ---------------------------------------------------------------------------
// K1: per-face gradient + tangent projection.
// ---------------------------------------------------------------------------
__global__ void k_grad(const int* __restrict__ Gc, const float* __restrict__ Gv,
                       const float* __restrict__ EW, const float* __restrict__ NS) {
    int c4 = threadIdx.x;                       // 0..15
    int f  = blockIdx.x * 16 + threadIdx.y;
    int b  = blockIdx.y;

    const float4* xin4 = (const float4*)d_xin + (size_t)b * NVT * 16;

    float4 aew = make_float4(0.f, 0.f, 0.f, 0.f);
    float4 ans = make_float4(0.f, 0.f, 0.f, 0.f);
    #pragma unroll
    for (int d = 0; d < 3; d++) {
        int row = d * NFC + f;
        float4 a = make_float4(0.f, 0.f, 0.f, 0.f);
        #pragma unroll
        for (int j = 0; j < 3; j++) {
            int   idx = 3 * row + j;
            int   col = Gc[idx];
            float w   = Gv[idx];
            float4 xv = xin4[(size_t)col * 16 + c4];
            a.x += w * xv.x; a.y += w * xv.y; a.z += w * xv.z; a.w += w * xv.w;
        }
        float ew = EW[f * 3 + d], ns = NS[f * 3 + d];
        aew.x += ew * a.x; aew.y += ew * a.y; aew.z += ew * a.z; aew.w += ew * a.w;
        ans.x += ns * a.x; ans.y += ns * a.y; ans.z += ns * a.z; ans.w += ns * a.w;
    }
    float4* gf4 = (float4*)d_gf + ((size_t)b * NFC + f) * 32;
    gf4[c4]      = aew;
    gf4[16 + c4] = ans;
}

// ---------------------------------------------------------------------------
// K2: fused gather into smem feat tile + register-tiled GEMM.
// 256 threads, TILE_V=64. GEMM: 8o x 2v per thread -> 16 FFMA per LDS.64.
// ---------------------------------------------------------------------------
#define TILE_V  64
#define FEAT_LD 68
#define SMEM_BYTES (256 * FEAT_LD * 4)

__global__ __launch_bounds__(256, 3) void k_fused(
    const int* __restrict__ Lc, const float* __restrict__ Lv,
    const int* __restrict__ Fc, const float* __restrict__ Fv,
    const float* __restrict__ bias, float* __restrict__ out)
{
    extern __shared__ float feat[];   // [256 p][FEAT_LD]
    int b     = blockIdx.y;
    int tile0 = blockIdx.x * TILE_V;
    int tid   = threadIdx.x;

    // -------- gather phase: 256 threads, each (c4, 4 vertices) --------
    {
        int c4 = tid & 15;        // float4 channel group (channels 4c4..4c4+3)
        int vg = tid >> 4;        // 0..15, 4 vertices each
        const float4* xin4 = (const float4*)d_xin + (size_t)b * NVT * 16;
        const float4* gf4  = (const float4*)d_gf  + (size_t)b * NFC * 32;

        #pragma unroll 1
        for (int i = 0; i < 4; i++) {
            int vloc = vg * 4 + i;
            int gv   = tile0 + vloc;
            if (gv >= NVT) break;

            // k=0: xin row
            float4 f0 = xin4[(size_t)gv * 16 + c4];

            // k=1: Laplacian (7 nnz)
            float4 f1 = make_float4(0.f, 0.f, 0.f, 0.f);
            {
                int base = gv * 7;
                #pragma unroll
                for (int j = 0; j < 7; j++) {
                    int   col = Lc[base + j];
                    float w   = Lv[base + j];
                    float4 xv = xin4[(size_t)col * 16 + c4];
                    f1.x += w * xv.x; f1.y += w * xv.y; f1.z += w * xv.z; f1.w += w * xv.w;
                }
            }

            // k=2,3: face->vertex average of projected gradients (6 nnz)
            float4 f2 = make_float4(0.f, 0.f, 0.f, 0.f);
            float4 f3 = make_float4(0.f, 0.f, 0.f, 0.f);
            {
                int base = gv * 6;
                #pragma unroll
                for (int j = 0; j < 6; j++) {
                    int   fc = Fc[base + j];
                    float w  = Fv[base + j];
                    const float4* gp = gf4 + (size_t)fc * 32;
                    float4 e4 = gp[c4];
                    float4 n4 = gp[16 + c4];
                    f2.x += w * e4.x; f2.y += w * e4.y; f2.z += w * e4.z; f2.w += w * e4.w;
                    f3.x += w * n4.x; f3.y += w * n4.y; f3.z += w * n4.z; f3.w += w * n4.w;
                }
            }

            // permuted rows: channel c=4*c4+j stored at row k*64 + j*16 + c4
            feat[(c4 +  0) * FEAT_LD + vloc] = f0.x;
            feat[(c4 + 16) * FEAT_LD + vloc] = f0.y;
            feat[(c4 + 32) * FEAT_LD + vloc] = f0.z;
            feat[(c4 + 48) * FEAT_LD + vloc] = f0.w;
            feat[(64 + c4 +  0) * FEAT_LD + vloc] = f1.x;
            feat[(64 + c4 + 16) * FEAT_LD + vloc] = f1.y;
            feat[(64 + c4 + 32) * FEAT_LD + vloc] = f1.z;
            feat[(64 + c4 + 48) * FEAT_LD + vloc] = f1.w;
            feat[(128 + c4 +  0) * FEAT_LD + vloc] = f2.x;
            feat[(128 + c4 + 16) * FEAT_LD + vloc] = f2.y;
            feat[(128 + c4 + 32) * FEAT_LD + vloc] = f2.z;
            feat[(128 + c4 + 48) * FEAT_LD + vloc] = f2.w;
            feat[(192 + c4 +  0) * FEAT_LD + vloc] = f3.x;
            feat[(192 + c4 + 16) * FEAT_LD + vloc] = f3.y;
            feat[(192 + c4 + 32) * FEAT_LD + vloc] = f3.z;
            feat[(192 + c4 + 48) * FEAT_LD + vloc] = f3.w;
        }
    }
    __syncthreads();

    // -------- GEMM phase: 8o x 2v register tile per thread --------
    {
        int og  = tid >> 5;          // 0..7  -> o0 = og*8
        int vg  = tid & 31;          // 0..31 -> vl0 = vg*2
        int o0  = og * 8;
        int vl0 = vg * 2;

        float acc[8][2];
        #pragma unroll
        for (int i = 0; i < 8; i++) {
            float bb = __ldg(&bias[o0 + i]);
            acc[i][0] = bb; acc[i][1] = bb;
        }

        const float4* cs4 = (const float4*)d_cs;
        #pragma unroll 4
        for (int kk = 0; kk < 256; kk++) {
            float4 a0 = __ldg(&cs4[kk * 16 + og * 2]);
            float4 a1 = __ldg(&cs4[kk * 16 + og * 2 + 1]);
            float2 fv = *(const float2*)&feat[kk * FEAT_LD + vl0];   // conflict-free LDS.64
            acc[0][0] += a0.x * fv.x; acc[0][1] += a0.x * fv.y;
            acc[1][0] += a0.y * fv.x; acc[1][1] += a0.y * fv.y;
            acc[2][0] += a0.z * fv.x; acc[2][1] += a0.z * fv.y;
            acc[3][0] += a0.w * fv.x; acc[3][1] += a0.w * fv.y;
            acc[4][0] += a1.x * fv.x; acc[4][1] += a1.x * fv.y;
            acc[5][0] += a1.y * fv.x; acc[5][1] += a1.y * fv.y;
            acc[6][0] += a1.z * fv.x; acc[6][1] += a1.z * fv.y;
            acc[7][0] += a1.w * fv.x; acc[7][1] += a1.w * fv.y;
        }

        int vbase = tile0 + vl0;
        #pragma unroll
        for (int i = 0; i < 8; i++) {
            // vbase is even and NVT is even -> 8B-aligned float2 store is safe.
            float* op = out + (size_t)(b * 64 + o0 + i) * NVT + vbase;
            if (vbase + 1 < NVT) {
                *(float2*)op = make_float2(acc[i][0], acc[i][1]);
            } else if (vbase < NVT) {
                op[0] = acc[i][0];
            }
        }
    }
}

// ---------------------------------------------------------------------------
extern "C" void kernel_launch(void* const* d_in, const int* in_sizes, int n_in,
                              void* d_out, int out_size) {
    (void)in_sizes; (void)n_in; (void)out_size;
    const float* x      = (const float*)d_in[0];
    const int*   Gc     = (const int*)  d_in[2];
    const float* Gv     = (const float*)d_in[3];
    const int*   Lc     = (const int*)  d_in[5];
    const float* Lv     = (const float*)d_in[6];
    const int*   Fc     = (const int*)  d_in[8];
    const float* Fv     = (const float*)d_in[9];
    const float* EW     = (const float*)d_in[10];
    const float* NS     = (const float*)d_in[11];
    const float* coeffs = (const float*)d_in[12];
    const float* bias   = (const float*)d_in[13];
    float* out = (float*)d_out;

    cudaFuncSetAttribute(k_fused, cudaFuncAttributeMaxDynamicSharedMemorySize, SMEM_BYTES);

    {
        dim3 bt(32, 8), gt((NVT + 31) / 32, 2, NB);
        k_transpose<<<gt, bt>>>(x);
    }
    k_coeffs<<<64, 256>>>(coeffs);
    {
        dim3 bg(16, 16), gg(NFC / 16, NB);
        k_grad<<<gg, bg>>>(Gc, Gv, EW, NS);
    }
    {
        dim3 gf((NVT + TILE_V - 1) / TILE_V, NB);
        k_fused<<<gf, 256, SMEM_BYTES>>>(Lc, Lv, Fc, Fv, bias, out);
    }
}

// round 6
// speedup vs baseline: 1.1958x; 1.1958x over previous
#include <cuda_runtime.h>
#include <stdint.h>

#define NB   8
#define NC   64      // CIN == COUT == 64
#define NVP  10242
#define NVT  40962
#define NFC  81920

// scratch (device globals — no allocation allowed)
__device__ float d_xin[(size_t)NB * NVT * NC];     // [b][v][c], padded region = 1.0
__device__ float d_gf [(size_t)NB * NFC * 128];    // [b][f][ew c0..63 | ns c0..63]
__device__ float d_cs [256 * 64];                  // [p][o], p = permuted (k,c) row

// ---------------------------------------------------------------------------
// K0: transpose x [B][C][NVP] -> d_xin [B][v][c], pad v>=NVP with 1.0
// ---------------------------------------------------------------------------
__global__ void k_transpose(const float* __restrict__ x) {
    __shared__ float tile[32][33];
    int b  = blockIdx.z;
    int v0 = blockIdx.x * 32;
    int c0 = blockIdx.y * 32;
    int tx = threadIdx.x, ty = threadIdx.y;   // 32 x 8
    #pragma unroll
    for (int i = 0; i < 4; i++) {
        int c = c0 + ty + i * 8;
        int v = v0 + tx;
        float val = 1.0f;
        if (v < NVP) val = x[((size_t)b * NC + c) * NVP + v];
        tile[ty + i * 8][tx] = val;
    }
    __syncthreads();
    #pragma unroll
    for (int i = 0; i < 4; i++) {
        int v = v0 + ty + i * 8;
        int c = c0 + tx;
        if (v < NVT)
            d_xin[((size_t)b * NVT + v) * NC + c] = tile[tx][ty + i * 8];
    }
}

// ---------------------------------------------------------------------------
// Kc: reorder coeffs [o][c][k] -> d_cs[p][o]
// physical row p = k*64 + j*16 + c4  where channel c = 4*c4 + j
// ---------------------------------------------------------------------------
__global__ void k_coeffs(const float* __restrict__ coeffs) {
    int idx = blockIdx.x * 256 + threadIdx.x;   // 0..16383
    int p = idx >> 6, o = idx & 63;
    int k  = p >> 6;
    int pr = p & 63;
    int j  = pr >> 4;
    int c4 = pr & 15;
    int c  = 4 * c4 + j;
    d_cs[idx] = coeffs[(o * 64 + c) * 4 + k];
}

// ---------------------------------------------------------------------------
// K1: per-face gradient + tangent projection.
// ---------------------------------------------------------------------------
__global__ void k_grad(const int* __restrict__ Gc, const float* __restrict__ Gv,
                       const float* __restrict__ EW, const float* __restrict__ NS) {
    int c4 = threadIdx.x;                       // 0..15
    int f  = blockIdx.x * 16 + threadIdx.y;
    int b  = blockIdx.y;

    const float4* xin4 = (const float4*)d_xin + (size_t)b * NVT * 16;

    float4 aew = make_float4(0.f, 0.f, 0.f, 0.f);
    float4 ans = make_float4(0.f, 0.f, 0.f, 0.f);
    #pragma unroll
    for (int d = 0; d < 3; d++) {
        int row = d * NFC + f;
        float4 a = make_float4(0.f, 0.f, 0.f, 0.f);
        #pragma unroll
        for (int j = 0; j < 3; j++) {
            int   idx = 3 * row + j;
            int   col = Gc[idx];
            float w   = Gv[idx];
            float4 xv = xin4[(size_t)col * 16 + c4];
            a.x += w * xv.x; a.y += w * xv.y; a.z += w * xv.z; a.w += w * xv.w;
        }
        float ew = EW[f * 3 + d], ns = NS[f * 3 + d];
        aew.x += ew * a.x; aew.y += ew * a.y; aew.z += ew * a.z; aew.w += ew * a.w;
        ans.x += ns * a.x; ans.y += ns * a.y; ans.z += ns * a.z; ans.w += ns * a.w;
    }
    float4* gf4 = (float4*)d_gf + ((size_t)b * NFC + f) * 32;
    gf4[c4]      = aew;
    gf4[16 + c4] = ans;
}

// ---------------------------------------------------------------------------
// K2: fused gather + GEMM, K split into two 128-row chunks to keep smem small.
// 256 threads, TILE_V=128, thread tile 4o x 8v, 3 blocks/SM.
// Chunk A: k=0 (xin), k=1 (laplacian).  Chunk B: k=2 (ew), k=3 (ns).
// ---------------------------------------------------------------------------
#define TILE_V  128
#define FEAT_LD 132
#define SMEM_BYTES (128 * FEAT_LD * 4)

__global__ __launch_bounds__(256, 3) void k_fused(
    const int* __restrict__ Lc, const float* __restrict__ Lv,
    const int* __restrict__ Fc, const float* __restrict__ Fv,
    const float* __restrict__ bias, float* __restrict__ out)
{
    extern __shared__ float feat[];   // [128 rows][FEAT_LD]
    int b     = blockIdx.y;
    int tile0 = blockIdx.x * TILE_V;
    int tid   = threadIdx.x;

    int c4 = tid & 15;        // gather: float4 channel group
    int vg = tid >> 4;        // gather: 0..15, 8 vertices each

    const float4* xin4 = (const float4*)d_xin + (size_t)b * NVT * 16;
    const float4* gf4  = (const float4*)d_gf  + (size_t)b * NFC * 32;

    // GEMM thread mapping (same tid, different decomposition)
    int og  = tid & 15;            // o0 = og*4
    int vgm = tid >> 4;            // vl0 = vgm*8
    int o0  = og * 4;
    int vl0 = vgm * 8;

    float acc[4][8];
    #pragma unroll
    for (int i = 0; i < 4; i++) {
        float bb = __ldg(&bias[o0 + i]);
        #pragma unroll
        for (int j = 0; j < 8; j++) acc[i][j] = bb;
    }

    const float4* cs4 = (const float4*)d_cs;

    // ================= chunk A: xin (rows 0..63) + laplacian (rows 64..127) ====
    #pragma unroll 1
    for (int i = 0; i < 8; i++) {
        int vloc = vg * 8 + i;
        int gv   = tile0 + vloc;
        if (gv >= NVT) break;

        float4 f0 = xin4[(size_t)gv * 16 + c4];

        float4 f1 = make_float4(0.f, 0.f, 0.f, 0.f);
        int base = gv * 7;
        #pragma unroll
        for (int j = 0; j < 7; j++) {
            int   col = Lc[base + j];
            float w   = Lv[base + j];
            float4 xv = xin4[(size_t)col * 16 + c4];
            f1.x += w * xv.x; f1.y += w * xv.y; f1.z += w * xv.z; f1.w += w * xv.w;
        }

        feat[(c4 +  0) * FEAT_LD + vloc] = f0.x;
        feat[(c4 + 16) * FEAT_LD + vloc] = f0.y;
        feat[(c4 + 32) * FEAT_LD + vloc] = f0.z;
        feat[(c4 + 48) * FEAT_LD + vloc] = f0.w;
        feat[(64 + c4 +  0) * FEAT_LD + vloc] = f1.x;
        feat[(64 + c4 + 16) * FEAT_LD + vloc] = f1.y;
        feat[(64 + c4 + 32) * FEAT_LD + vloc] = f1.z;
        feat[(64 + c4 + 48) * FEAT_LD + vloc] = f1.w;
    }
    __syncthreads();

    #pragma unroll 4
    for (int kk = 0; kk < 128; kk++) {
        float4 a  = __ldg(&cs4[kk * 16 + og]);
        float4 b0 = *(const float4*)&feat[kk * FEAT_LD + vl0];
        float4 b1 = *(const float4*)&feat[kk * FEAT_LD + vl0 + 4];
        acc[0][0] += a.x*b0.x; acc[0][1] += a.x*b0.y; acc[0][2] += a.x*b0.z; acc[0][3] += a.x*b0.w;
        acc[0][4] += a.x*b1.x; acc[0][5] += a.x*b1.y; acc[0][6] += a.x*b1.z; acc[0][7] += a.x*b1.w;
        acc[1][0] += a.y*b0.x; acc[1][1] += a.y*b0.y; acc[1][2] += a.y*b0.z; acc[1][3] += a.y*b0.w;
        acc[1][4] += a.y*b1.x; acc[1][5] += a.y*b1.y; acc[1][6] += a.y*b1.z; acc[1][7] += a.y*b1.w;
        acc[2][0] += a.z*b0.x; acc[2][1] += a.z*b0.y; acc[2][2] += a.z*b0.z; acc[2][3] += a.z*b0.w;
        acc[2][4] += a.z*b1.x; acc[2][5] += a.z*b1.y; acc[2][6] += a.z*b1.z; acc[2][7] += a.z*b1.w;
        acc[3][0] += a.w*b0.x; acc[3][1] += a.w*b0.y; acc[3][2] += a.w*b0.z; acc[3][3] += a.w*b0.w;
        acc[3][4] += a.w*b1.x; acc[3][5] += a.w*b1.y; acc[3][6] += a.w*b1.z; acc[3][7] += a.w*b1.w;
    }
    __syncthreads();   // everyone done reading chunk A before overwrite

    // ================= chunk B: grad_ew (rows 0..63) + grad_ns (rows 64..127) ==
    #pragma unroll 1
    for (int i = 0; i < 8; i++) {
        int vloc = vg * 8 + i;
        int gv   = tile0 + vloc;
        if (gv >= NVT) break;

        float4 f2 = make_float4(0.f, 0.f, 0.f, 0.f);
        float4 f3 = make_float4(0.f, 0.f, 0.f, 0.f);
        int base = gv * 6;
        #pragma unroll
        for (int j = 0; j < 6; j++) {
            int   fc = Fc[base + j];
            float w  = Fv[base + j];
            const float4* gp = gf4 + (size_t)fc * 32;
            float4 e4 = gp[c4];
            float4 n4 = gp[16 + c4];
            f2.x += w * e4.x; f2.y += w * e4.y; f2.z += w * e4.z; f2.w += w * e4.w;
            f3.x += w * n4.x; f3.y += w * n4.y; f3.z += w * n4.z; f3.w += w * n4.w;
        }

        feat[(c4 +  0) * FEAT_LD + vloc] = f2.x;
        feat[(c4 + 16) * FEAT_LD + vloc] = f2.y;
        feat[(c4 + 32) * FEAT_LD + vloc] = f2.z;
        feat[(c4 + 48) * FEAT_LD + vloc] = f2.w;
        feat[(64 + c4 +  0) * FEAT_LD + vloc] = f3.x;
        feat[(64 + c4 + 16) * FEAT_LD + vloc] = f3.y;
        feat[(64 + c4 + 32) * FEAT_LD + vloc] = f3.z;
        feat[(64 + c4 + 48) * FEAT_LD + vloc] = f3.w;
    }
    __syncthreads();

    #pragma unroll 4
    for (int kk = 0; kk < 128; kk++) {
        float4 a  = __ldg(&cs4[(128 + kk) * 16 + og]);
        float4 b0 = *(const float4*)&feat[kk * FEAT_LD + vl0];
        float4 b1 = *(const float4*)&feat[kk * FEAT_LD + vl0 + 4];
        acc[0][0] += a.x*b0.x; acc[0][1] += a.x*b0.y; acc[0][2] += a.x*b0.z; acc[0][3] += a.x*b0.w;
        acc[0][4] += a.x*b1.x; acc[0][5] += a.x*b1.y; acc[0][6] += a.x*b1.z; acc[0][7] += a.x*b1.w;
        acc[1][0] += a.y*b0.x; acc[1][1] += a.y*b0.y; acc[1][2] += a.y*b0.z; acc[1][3] += a.y*b0.w;
        acc[1][4] += a.y*b1.x; acc[1][5] += a.y*b1.y; acc[1][6] += a.y*b1.z; acc[1][7] += a.y*b1.w;
        acc[2][0] += a.z*b0.x; acc[2][1] += a.z*b0.y; acc[2][2] += a.z*b0.z; acc[2][3] += a.z*b0.w;
        acc[2][4] += a.z*b1.x; acc[2][5] += a.z*b1.y; acc[2][6] += a.z*b1.z; acc[2][7] += a.z*b1.w;
        acc[3][0] += a.w*b0.x; acc[3][1] += a.w*b0.y; acc[3][2] += a.w*b0.z; acc[3][3] += a.w*b0.w;
        acc[3][4] += a.w*b1.x; acc[3][5] += a.w*b1.y; acc[3][6] += a.w*b1.z; acc[3][7] += a.w*b1.w;
    }

    // ================= store 4o x 8v (float2: rows only 8B-aligned) ===========
    int vbase = tile0 + vl0;
    #pragma unroll
    for (int i = 0; i < 4; i++) {
        float* op = out + (size_t)(b * 64 + o0 + i) * NVT + vbase;
        if (vbase + 7 < NVT) {
            *(float2*)(op)     = make_float2(acc[i][0], acc[i][1]);
            *(float2*)(op + 2) = make_float2(acc[i][2], acc[i][3]);
            *(float2*)(op + 4) = make_float2(acc[i][4], acc[i][5]);
            *(float2*)(op + 6) = make_float2(acc[i][6], acc[i][7]);
        } else {
            #pragma unroll
            for (int j = 0; j < 8; j++)
                if (vbase + j < NVT) op[j] = acc[i][j];
        }
    }
}

// ---------------------------------------------------------------------------
extern "C" void kernel_launch(void* const* d_in, const int* in_sizes, int n_in,
                              void* d_out, int out_size) {
    (void)in_sizes; (void)n_in; (void)out_size;
    const float* x      = (const float*)d_in[0];
    const int*   Gc     = (const int*)  d_in[2];
    const float* Gv     = (const float*)d_in[3];
    const int*   Lc     = (const int*)  d_in[5];
    const float* Lv     = (const float*)d_in[6];
    const int*   Fc     = (const int*)  d_in[8];
    const float* Fv     = (const float*)d_in[9];
    const float* EW     = (const float*)d_in[10];
    const float* NS     = (const float*)d_in[11];
    const float* coeffs = (const float*)d_in[12];
    const float* bias   = (const float*)d_in[13];
    float* out = (float*)d_out;

    cudaFuncSetAttribute(k_fused, cudaFuncAttributeMaxDynamicSharedMemorySize, SMEM_BYTES);

    {
        dim3 bt(32, 8), gt((NVT + 31) / 32, 2, NB);
        k_transpose<<<gt, bt>>>(x);
    }
    k_coeffs<<<64, 256>>>(coeffs);
    {
        dim3 bg(16, 16), gg(NFC / 16, NB);
        k_grad<<<gg, bg>>>(Gc, Gv, EW, NS);
    }
    {
        dim3 gf((NVT + TILE_V - 1) / TILE_V, NB);
        k_fused<<<gf, 256, SMEM_BYTES>>>(Lc, Lv, Fc, Fv, bias, out);
    }
}

// round 7
// speedup vs baseline: 1.2353x; 1.0330x over previous
#include <cuda_runtime.h>
#include <stdint.h>

#define NB   8
#define NC   64      // CIN == COUT == 64
#define NVP  10242
#define NVT  40962
#define NFC  81920

// scratch (device globals — no allocation allowed)
__device__ float d_xin[(size_t)NB * NVT * NC];     // [b][v][c], padded region = 1.0
__device__ float d_gf [(size_t)NB * NFC * 128];    // [b][f][ew c0..63 | ns c0..63]
__device__ float d_cs [256 * 64];                  // [p][o], p = permuted (k,c) row

// ---- packed fp32x2 helpers (Blackwell) ------------------------------------
__device__ __forceinline__ uint64_t pack2(float lo, float hi) {
    uint64_t r;
    asm("mov.b64 %0, {%1, %2};" : "=l"(r) : "f"(lo), "f"(hi));
    return r;
}
__device__ __forceinline__ void fma2(uint64_t& d, uint64_t a, uint64_t b) {
    asm("fma.rn.f32x2 %0, %1, %2, %3;" : "=l"(d) : "l"(a), "l"(b), "l"(d));
}
__device__ __forceinline__ float2 unpack2(uint64_t v) {
    float2 r;
    r.x = __uint_as_float((uint32_t)(v & 0xFFFFFFFFull));
    r.y = __uint_as_float((uint32_t)(v >> 32));
    return r;
}

// ---------------------------------------------------------------------------
// K0: transpose x [B][C][NVP] -> d_xin [B][v][c], pad v>=NVP with 1.0
// ---------------------------------------------------------------------------
__global__ void k_transpose(const float* __restrict__ x) {
    __shared__ float tile[32][33];
    int b  = blockIdx.z;
    int v0 = blockIdx.x * 32;
    int c0 = blockIdx.y * 32;
    int tx = threadIdx.x, ty = threadIdx.y;   // 32 x 8
    #pragma unroll
    for (int i = 0; i < 4; i++) {
        int c = c0 + ty + i * 8;
        int v = v0 + tx;
        float val = 1.0f;
        if (v < NVP) val = x[((size_t)b * NC + c) * NVP + v];
        tile[ty + i * 8][tx] = val;
    }
    __syncthreads();
    #pragma unroll
    for (int i = 0; i < 4; i++) {
        int v = v0 + ty + i * 8;
        int c = c0 + tx;
        if (v < NVT)
            d_xin[((size_t)b * NVT + v) * NC + c] = tile[tx][ty + i * 8];
    }
}

// ---------------------------------------------------------------------------
// Kc: reorder coeffs [o][c][k] -> d_cs[p][o]
// physical row p = k*64 + j*16 + c4  where channel c = 4*c4 + j
// ---------------------------------------------------------------------------
__global__ void k_coeffs(const float* __restrict__ coeffs) {
    int idx = blockIdx.x * 256 + threadIdx.x;   // 0..16383
    int p = idx >> 6, o = idx & 63;
    int k  = p >> 6;
    int pr = p & 63;
    int j  = pr >> 4;
    int c4 = pr & 15;
    int c  = 4 * c4 + j;
    d_cs[idx] = coeffs[(o * 64 + c) * 4 + k];
}

// ---------------------------------------------------------------------------
// K1: per-face gradient + tangent projection.
// ---------------------------------------------------------------------------
__global__ void k_grad(const int* __restrict__ Gc, const float* __restrict__ Gv,
                       const float* __restrict__ EW, const float* __restrict__ NS) {
    int c4 = threadIdx.x;                       // 0..15
    int f  = blockIdx.x * 16 + threadIdx.y;
    int b  = blockIdx.y;

    const float4* xin4 = (const float4*)d_xin + (size_t)b * NVT * 16;

    float4 aew = make_float4(0.f, 0.f, 0.f, 0.f);
    float4 ans = make_float4(0.f, 0.f, 0.f, 0.f);
    #pragma unroll
    for (int d = 0; d < 3; d++) {
        int row = d * NFC + f;
        float4 a = make_float4(0.f, 0.f, 0.f, 0.f);
        #pragma unroll
        for (int j = 0; j < 3; j++) {
            int   idx = 3 * row + j;
            int   col = Gc[idx];
            float w   = Gv[idx];
            float4 xv = xin4[(size_t)col * 16 + c4];
            a.x += w * xv.x; a.y += w * xv.y; a.z += w * xv.z; a.w += w * xv.w;
        }
        float ew = EW[f * 3 + d], ns = NS[f * 3 + d];
        aew.x += ew * a.x; aew.y += ew * a.y; aew.z += ew * a.z; aew.w += ew * a.w;
        ans.x += ns * a.x; ans.y += ns * a.y; ans.z += ns * a.z; ans.w += ns * a.w;
    }
    float4* gf4 = (float4*)d_gf + ((size_t)b * NFC + f) * 32;
    gf4[c4]      = aew;
    gf4[16 + c4] = ans;
}

// ---------------------------------------------------------------------------
// K2: fused gather + GEMM, K split into two 128-row chunks.
// 256 threads, TILE_V=128, thread tile 4o x 8v, fma.rn.f32x2 accumulators.
// ---------------------------------------------------------------------------
#define TILE_V  128
#define FEAT_LD 132
#define SMEM_BYTES (128 * FEAT_LD * 4)

__global__ __launch_bounds__(256, 3) void k_fused(
    const int* __restrict__ Lc, const float* __restrict__ Lv,
    const int* __restrict__ Fc, const float* __restrict__ Fv,
    const float* __restrict__ bias, float* __restrict__ out)
{
    extern __shared__ float feat[];   // [128 rows][FEAT_LD]
    int b     = blockIdx.y;
    int tile0 = blockIdx.x * TILE_V;
    int tid   = threadIdx.x;

    int c4 = tid & 15;        // gather: float4 channel group
    int vg = tid >> 4;        // gather: 0..15, 8 vertices each

    const float4* xin4 = (const float4*)d_xin + (size_t)b * NVT * 16;
    const float4* gf4  = (const float4*)d_gf  + (size_t)b * NFC * 32;

    // GEMM thread mapping
    int og  = tid & 15;            // o0 = og*4
    int vgm = tid >> 4;            // vl0 = vgm*8
    int o0  = og * 4;
    int vl0 = vgm * 8;

    // accumulators: 4 o-rows x 4 v-pairs, packed f32x2
    uint64_t acc[4][4];
    #pragma unroll
    for (int i = 0; i < 4; i++) {
        float bb = __ldg(&bias[o0 + i]);
        uint64_t bb2 = pack2(bb, bb);
        #pragma unroll
        for (int j = 0; j < 4; j++) acc[i][j] = bb2;
    }

    const float4* cs4 = (const float4*)d_cs;

    // ================= chunk A: xin (rows 0..63) + laplacian (rows 64..127) ====
    #pragma unroll 1
    for (int i = 0; i < 8; i++) {
        int vloc = vg * 8 + i;
        int gv   = tile0 + vloc;
        if (gv >= NVT) break;

        float4 f0 = xin4[(size_t)gv * 16 + c4];

        float4 f1 = make_float4(0.f, 0.f, 0.f, 0.f);
        int base = gv * 7;
        #pragma unroll
        for (int j = 0; j < 7; j++) {
            int   col = Lc[base + j];
            float w   = Lv[base + j];
            float4 xv = xin4[(size_t)col * 16 + c4];
            f1.x += w * xv.x; f1.y += w * xv.y; f1.z += w * xv.z; f1.w += w * xv.w;
        }

        feat[(c4 +  0) * FEAT_LD + vloc] = f0.x;
        feat[(c4 + 16) * FEAT_LD + vloc] = f0.y;
        feat[(c4 + 32) * FEAT_LD + vloc] = f0.z;
        feat[(c4 + 48) * FEAT_LD + vloc] = f0.w;
        feat[(64 + c4 +  0) * FEAT_LD + vloc] = f1.x;
        feat[(64 + c4 + 16) * FEAT_LD + vloc] = f1.y;
        feat[(64 + c4 + 32) * FEAT_LD + vloc] = f1.z;
        feat[(64 + c4 + 48) * FEAT_LD + vloc] = f1.w;
    }
    __syncthreads();

    #pragma unroll 4
    for (int kk = 0; kk < 128; kk++) {
        float4 a = __ldg(&cs4[kk * 16 + og]);
        uint64_t ax = pack2(a.x, a.x), ay = pack2(a.y, a.y);
        uint64_t az = pack2(a.z, a.z), aw = pack2(a.w, a.w);
        ulonglong2 b01 = *(const ulonglong2*)&feat[kk * FEAT_LD + vl0];     // v pairs 0,1
        ulonglong2 b23 = *(const ulonglong2*)&feat[kk * FEAT_LD + vl0 + 4]; // v pairs 2,3
        fma2(acc[0][0], ax, b01.x); fma2(acc[0][1], ax, b01.y); fma2(acc[0][2], ax, b23.x); fma2(acc[0][3], ax, b23.y);
        fma2(acc[1][0], ay, b01.x); fma2(acc[1][1], ay, b01.y); fma2(acc[1][2], ay, b23.x); fma2(acc[1][3], ay, b23.y);
        fma2(acc[2][0], az, b01.x); fma2(acc[2][1], az, b01.y); fma2(acc[2][2], az, b23.x); fma2(acc[2][3], az, b23.y);
        fma2(acc[3][0], aw, b01.x); fma2(acc[3][1], aw, b01.y); fma2(acc[3][2], aw, b23.x); fma2(acc[3][3], aw, b23.y);
    }
    __syncthreads();   // everyone done reading chunk A before overwrite

    // ================= chunk B: grad_ew (rows 0..63) + grad_ns (rows 64..127) ==
    #pragma unroll 1
    for (int i = 0; i < 8; i++) {
        int vloc = vg * 8 + i;
        int gv   = tile0 + vloc;
        if (gv >= NVT) break;

        float4 f2 = make_float4(0.f, 0.f, 0.f, 0.f);
        float4 f3 = make_float4(0.f, 0.f, 0.f, 0.f);
        int base = gv * 6;
        #pragma unroll
        for (int j = 0; j < 6; j++) {
            int   fc = Fc[base + j];
            float w  = Fv[base + j];
            const float4* gp = gf4 + (size_t)fc * 32;
            float4 e4 = gp[c4];
            float4 n4 = gp[16 + c4];
            f2.x += w * e4.x; f2.y += w * e4.y; f2.z += w * e4.z; f2.w += w * e4.w;
            f3.x += w * n4.x; f3.y += w * n4.y; f3.z += w * n4.z; f3.w += w * n4.w;
        }

        feat[(c4 +  0) * FEAT_LD + vloc] = f2.x;
        feat[(c4 + 16) * FEAT_LD + vloc] = f2.y;
        feat[(c4 + 32) * FEAT_LD + vloc] = f2.z;
        feat[(c4 + 48) * FEAT_LD + vloc] = f2.w;
        feat[(64 + c4 +  0) * FEAT_LD + vloc] = f3.x;
        feat[(64 + c4 + 16) * FEAT_LD + vloc] = f3.y;
        feat[(64 + c4 + 32) * FEAT_LD + vloc] = f3.z;
        feat[(64 + c4 + 48) * FEAT_LD + vloc] = f3.w;
    }
    __syncthreads();

    #pragma unroll 4
    for (int kk = 0; kk < 128; kk++) {
        float4 a = __ldg(&cs4[(128 + kk) * 16 + og]);
        uint64_t ax = pack2(a.x, a.x), ay = pack2(a.y, a.y);
        uint64_t az = pack2(a.z, a.z), aw = pack2(a.w, a.w);
        ulonglong2 b01 = *(const ulonglong2*)&feat[kk * FEAT_LD + vl0];
        ulonglong2 b23 = *(const ulonglong2*)&feat[kk * FEAT_LD + vl0 + 4];
        fma2(acc[0][0], ax, b01.x); fma2(acc[0][1], ax, b01.y); fma2(acc[0][2], ax, b23.x); fma2(acc[0][3], ax, b23.y);
        fma2(acc[1][0], ay, b01.x); fma2(acc[1][1], ay, b01.y); fma2(acc[1][2], ay, b23.x); fma2(acc[1][3], ay, b23.y);
        fma2(acc[2][0], az, b01.x); fma2(acc[2][1], az, b01.y); fma2(acc[2][2], az, b23.x); fma2(acc[2][3], az, b23.y);
        fma2(acc[3][0], aw, b01.x); fma2(acc[3][1], aw, b01.y); fma2(acc[3][2], aw, b23.x); fma2(acc[3][3], aw, b23.y);
    }

    // ================= store 4o x 8v (float2: rows only 8B-aligned) ===========
    int vbase = tile0 + vl0;
    #pragma unroll
    for (int i = 0; i < 4; i++) {
        float* op = out + (size_t)(b * 64 + o0 + i) * NVT + vbase;
        if (vbase + 7 < NVT) {
            *(float2*)(op)     = unpack2(acc[i][0]);
            *(float2*)(op + 2) = unpack2(acc[i][1]);
            *(float2*)(op + 4) = unpack2(acc[i][2]);
            *(float2*)(op + 6) = unpack2(acc[i][3]);
        } else {
            #pragma unroll
            for (int j = 0; j < 4; j++) {
                float2 r = unpack2(acc[i][j]);
                if (vbase + 2 * j     < NVT) op[2 * j]     = r.x;
                if (vbase + 2 * j + 1 < NVT) op[2 * j + 1] = r.y;
            }
        }
    }
}

// ---------------------------------------------------------------------------
extern "C" void kernel_launch(void* const* d_in, const int* in_sizes, int n_in,
                              void* d_out, int out_size) {
    (void)in_sizes; (void)n_in; (void)out_size;
    const float* x      = (const float*)d_in[0];
    const int*   Gc     = (const int*)  d_in[2];
    const float* Gv     = (const float*)d_in[3];
    const int*   Lc     = (const int*)  d_in[5];
    const float* Lv     = (const float*)d_in[6];
    const int*   Fc     = (const int*)  d_in[8];
    const float* Fv     = (const float*)d_in[9];
    const float* EW     = (const float*)d_in[10];
    const float* NS     = (const float*)d_in[11];
    const float* coeffs = (const float*)d_in[12];
    const float* bias   = (const float*)d_in[13];
    float* out = (float*)d_out;

    cudaFuncSetAttribute(k_fused, cudaFuncAttributeMaxDynamicSharedMemorySize, SMEM_BYTES);

    {
        dim3 bt(32, 8), gt((NVT + 31) / 32, 2, NB);
        k_transpose<<<gt, bt>>>(x);
    }
    k_coeffs<<<64, 256>>>(coeffs);
    {
        dim3 bg(16, 16), gg(NFC / 16, NB);
        k_grad<<<gg, bg>>>(Gc, Gv, EW, NS);
    }
    {
        dim3 gf((NVT + TILE_V - 1) / TILE_V, NB);
        k_fused<<<gf, 256, SMEM_BYTES>>>(Lc, Lv, Fc, Fv, bias, out);
    }
}